// round 1
// baseline (speedup 1.0000x reference)
#include <cuda_runtime.h>
#include <math.h>

#define N_NODES 100000
#define E_MAX   1600000
#define ET_MAX  (E_MAX + N_NODES)
#define HID     64
#define IN_DIM  128
#define NCLS    40

// ---------------- scratch (device globals; no allocation allowed) ----------
__device__ float    g_h[(size_t)N_NODES * HID];    // transformed features h = in @ W
__device__ float    g_acc[(size_t)N_NODES * HID];  // aggregation accumulator / next input
__device__ float    g_s[N_NODES];
__device__ float    g_d[N_NODES];
__device__ unsigned g_mord[N_NODES];               // order-encoded segment max
__device__ float    g_denom[N_NODES];
__device__ float    g_e[ET_MAX];                   // per-edge logit, then prob
__device__ int      g_is64;                        // edge_index dtype flag

// ---------------- helpers ---------------------------------------------------
__device__ __forceinline__ unsigned f2ord(float f) {
    unsigned u = __float_as_uint(f);
    return (u & 0x80000000u) ? ~u : (u | 0x80000000u);
}
__device__ __forceinline__ float ord2f(unsigned u) {
    return (u & 0x80000000u) ? __uint_as_float(u & 0x7fffffffu)
                             : __uint_as_float(~u);
}

__device__ __forceinline__ void load_edge(const void* ei, int i, int E,
                                          int& src, int& dst) {
    if (i >= E) { int n = i - E; src = n; dst = n; return; }   // self-loop
    if (g_is64) {
        const long long* p = (const long long*)ei;
        src = (int)p[i];
        dst = (int)p[(long long)E + i];
    } else {
        const int* p = (const int*)ei;
        src = p[i];
        dst = p[E + i];
    }
}

// ---------------- kernels ---------------------------------------------------

// Detect whether edge_index is int64 (hi 32-bit words all zero) or int32.
__global__ void detect_kernel(const void* ei) {
    if (threadIdx.x == 0 && blockIdx.x == 0) {
        const int* p = (const int*)ei;
        int is64 = 1;
        for (int i = 0; i < 1024; i++) {
            if (p[2 * i + 1] != 0) { is64 = 0; break; }
        }
        g_is64 = is64;
    }
}

// O[n, 0:64] = A[n, 0:K] @ W[K, 64].  16 rows/block, 4 cols/thread.
template <int K>
__global__ void gemm64_kernel(const float* __restrict__ A,
                              const float* __restrict__ W,
                              float* __restrict__ O, int n) {
    __shared__ float ws[K * 64];
    __shared__ float xs[16][K];
    int tid = threadIdx.x;
    for (int i = tid; i < K * 64; i += 256) ws[i] = W[i];
    int row0 = blockIdx.x * 16;
    for (int i = tid; i < 16 * K; i += 256) {
        int r = i / K, c = i % K;
        int gr = row0 + r;
        xs[r][c] = (gr < n) ? A[(size_t)gr * K + c] : 0.f;
    }
    __syncthreads();
    int lr = tid >> 4;   // 0..15 local row
    int cg = tid & 15;   // 0..15 col group (4 cols)
    float4 acc = make_float4(0.f, 0.f, 0.f, 0.f);
    const float4* ws4 = (const float4*)ws;
#pragma unroll 8
    for (int k = 0; k < K; k++) {
        float  xv = xs[lr][k];
        float4 w  = ws4[k * 16 + cg];
        acc.x += xv * w.x; acc.y += xv * w.y;
        acc.z += xv * w.z; acc.w += xv * w.w;
    }
    int gr = row0 + lr;
    if (gr < n) ((float4*)O)[(size_t)gr * 16 + cg] = acc;
}

// Per node: s = h·a_s, d = h·a_d; also init mord/denom and zero accumulator.
__global__ void sd_kernel(const float* __restrict__ h,
                          const float* __restrict__ a_s,
                          const float* __restrict__ a_d, int n) {
    int warp = (blockIdx.x * blockDim.x + threadIdx.x) >> 5;
    int lane = threadIdx.x & 31;
    if (warp >= n) return;
    const float* hr = h + (size_t)warp * HID;
    float h0 = hr[lane], h1 = hr[lane + 32];
    float s = h0 * a_s[lane] + h1 * a_s[lane + 32];
    float d = h0 * a_d[lane] + h1 * a_d[lane + 32];
#pragma unroll
    for (int o = 16; o; o >>= 1) {
        s += __shfl_xor_sync(0xffffffffu, s, o);
        d += __shfl_xor_sync(0xffffffffu, d, o);
    }
    if (lane == 0) {
        g_s[warp] = s;
        g_d[warp] = d;
        g_mord[warp]  = 0u;     // < f2ord(x) for all finite x
        g_denom[warp] = 0.f;
    }
    g_acc[(size_t)warp * HID + lane]      = 0.f;
    g_acc[(size_t)warp * HID + lane + 32] = 0.f;
}

__global__ void edge_max_kernel(const void* ei, int E, int ET) {
    int i = blockIdx.x * blockDim.x + threadIdx.x;
    if (i >= ET) return;
    int src, dst;
    load_edge(ei, i, E, src, dst);
    float e = g_s[src] + g_d[dst];
    e = e > 0.f ? e : 0.2f * e;          // leaky_relu(0.2)
    g_e[i] = e;
    atomicMax(&g_mord[dst], f2ord(e));
}

__global__ void edge_expsum_kernel(const void* ei, int E, int ET) {
    int i = blockIdx.x * blockDim.x + threadIdx.x;
    if (i >= ET) return;
    int src, dst;
    load_edge(ei, i, E, src, dst);
    float m = ord2f(g_mord[dst]);
    float p = __expf(g_e[i] - m);
    g_e[i] = p;
    atomicAdd(&g_denom[dst], p);
}

// warp per edge: acc[dst] += alpha * h[src]
__global__ void edge_agg_kernel(const void* ei, int E, int ET) {
    int w    = (blockIdx.x * blockDim.x + threadIdx.x) >> 5;
    int lane = threadIdx.x & 31;
    if (w >= ET) return;
    int src, dst;
    load_edge(ei, w, E, src, dst);
    float p     = g_e[w];
    float alpha = p / (g_denom[dst] + 1e-16f);
    const float* hs = g_h   + (size_t)src * HID;
    float*       od = g_acc + (size_t)dst * HID;
    atomicAdd(od + lane,      alpha * hs[lane]);
    atomicAdd(od + lane + 32, alpha * hs[lane + 32]);
}

// in place: a = elu(a + b[c])
__global__ void bias_elu_kernel(float* __restrict__ a,
                                const float* __restrict__ b, int total) {
    int i = blockIdx.x * blockDim.x + threadIdx.x;
    if (i >= total) return;
    float v = a[i] + b[i & (HID - 1)];
    a[i] = v > 0.f ? v : expm1f(v);
}

// out[n, c] = h[n, :] @ Wl[:, c] + bl[c].  8 nodes x 40 cols per block (320 thr)
__global__ void logits_kernel(const float* __restrict__ h,
                              const float* __restrict__ Wl,
                              const float* __restrict__ bl,
                              float* __restrict__ out, int n) {
    __shared__ float ws[HID * NCLS];
    __shared__ float bs[NCLS];
    __shared__ float hs[8][HID];
    int tid = threadIdx.x;
    for (int i = tid; i < HID * NCLS; i += 320) ws[i] = Wl[i];
    if (tid < NCLS) bs[tid] = bl[tid];
    int node0 = blockIdx.x * 8;
    for (int i = tid; i < 8 * HID; i += 320) {
        int gi = node0 * HID + i;
        hs[i / HID][i % HID] = (node0 + i / HID < n) ? h[gi] : 0.f;
    }
    __syncthreads();
    int lr = tid / NCLS;     // 0..7
    int c  = tid - lr * NCLS;
    if (lr >= 8) return;
    float acc = bs[c];
#pragma unroll
    for (int k = 0; k < HID; k++) acc += hs[lr][k] * ws[k * NCLS + c];
    int node = node0 + lr;
    if (node < n) out[(size_t)node * NCLS + c] = acc;
}

// ---------------- launcher --------------------------------------------------
extern "C" void kernel_launch(void* const* d_in, const int* in_sizes, int n_in,
                              void* d_out, int out_size) {
    const float* x    = (const float*)d_in[0];
    const void*  ei   = d_in[1];
    const float* W0   = (const float*)d_in[2];
    const float* a_s0 = (const float*)d_in[3];
    const float* a_d0 = (const float*)d_in[4];
    const float* b0   = (const float*)d_in[5];
    const float* W1   = (const float*)d_in[6];
    const float* a_s1 = (const float*)d_in[7];
    const float* a_d1 = (const float*)d_in[8];
    const float* b1   = (const float*)d_in[9];
    const float* Wl   = (const float*)d_in[10];
    const float* bl   = (const float*)d_in[11];
    float* out = (float*)d_out;

    int n  = in_sizes[0] / IN_DIM;      // 100000
    int E  = in_sizes[1] / 2;           // 1600000 (elements / 2, dtype-agnostic)
    int ET = E + n;

    float* hbuf;  cudaGetSymbolAddress((void**)&hbuf, g_h);
    float* abuf;  cudaGetSymbolAddress((void**)&abuf, g_acc);

    int nodeWarpBlocks = (n + 7) / 8;          // sd: 8 warps/block
    int edgeBlocks     = (ET + 255) / 256;     // thread/edge
    int edgeWarpBlocks = (ET + 7) / 8;         // warp/edge
    int elemBlocks     = (n * HID + 255) / 256;

    detect_kernel<<<1, 32>>>(ei);

    // ---- layer 0 ----
    gemm64_kernel<IN_DIM><<<(n + 15) / 16, 256>>>(x, W0, hbuf, n);
    sd_kernel<<<nodeWarpBlocks, 256>>>(hbuf, a_s0, a_d0, n);
    edge_max_kernel<<<edgeBlocks, 256>>>(ei, E, ET);
    edge_expsum_kernel<<<edgeBlocks, 256>>>(ei, E, ET);
    edge_agg_kernel<<<edgeWarpBlocks, 256>>>(ei, E, ET);
    bias_elu_kernel<<<elemBlocks, 256>>>(abuf, b0, n * HID);

    // ---- layer 1 ----
    gemm64_kernel<HID><<<(n + 15) / 16, 256>>>(abuf, W1, hbuf, n);
    sd_kernel<<<nodeWarpBlocks, 256>>>(hbuf, a_s1, a_d1, n);
    edge_max_kernel<<<edgeBlocks, 256>>>(ei, E, ET);
    edge_expsum_kernel<<<edgeBlocks, 256>>>(ei, E, ET);
    edge_agg_kernel<<<edgeWarpBlocks, 256>>>(ei, E, ET);
    bias_elu_kernel<<<elemBlocks, 256>>>(abuf, b1, n * HID);

    // ---- head ----
    logits_kernel<<<(n + 7) / 8, 320>>>(abuf, Wl, bl, out, n);
}

// round 2
// speedup vs baseline: 3.0294x; 3.0294x over previous
#include <cuda_runtime.h>
#include <math.h>

#define N_NODES 100000
#define E_MAX   1600000
#define ET_MAX  (E_MAX + N_NODES)
#define HID     64
#define IN_DIM  128
#define NCLS    40
#define SCAN_CHUNK 1024

// ---------------- scratch (device globals; no allocation allowed) ----------
__device__ float g_h[(size_t)N_NODES * HID];    // transformed features h = in @ W
__device__ float g_acc[(size_t)N_NODES * HID];  // layer output / next input
__device__ float g_s[N_NODES];
__device__ float g_d[N_NODES];
__device__ int   g_deg[N_NODES];
__device__ int   g_tmp[N_NODES];
__device__ int   g_rowptr[N_NODES];
__device__ int   g_cursor[N_NODES];             // after fill: row end
__device__ int   g_bsum[128];
__device__ int   g_csr[ET_MAX];                 // src per edge, grouped by dst
__device__ int   g_is64;

// ---------------- helpers ---------------------------------------------------
__device__ __forceinline__ void load_edge(const void* ei, int i, int E,
                                          int& src, int& dst) {
    if (i >= E) { int v = i - E; src = v; dst = v; return; }   // self-loop
    if (g_is64) {
        const long long* p = (const long long*)ei;
        src = (int)p[i];
        dst = (int)p[(long long)E + i];
    } else {
        const int* p = (const int*)ei;
        src = p[i];
        dst = p[E + i];
    }
}

// ---------------- dtype detect ----------------------------------------------
__global__ void detect_kernel(const void* ei) {
    if (threadIdx.x == 0) {
        const int* p = (const int*)ei;
        int is64 = 1;
        for (int i = 0; i < 1024; i++)
            if (p[2 * i + 1] != 0) { is64 = 0; break; }
        g_is64 = is64;
    }
}

// ---------------- CSR build --------------------------------------------------
__global__ void zero_deg_kernel(int n) {
    int i = blockIdx.x * blockDim.x + threadIdx.x;
    if (i < n) g_deg[i] = 0;
}

__global__ void hist_kernel(const void* ei, int E, int ET) {
    int i = blockIdx.x * blockDim.x + threadIdx.x;
    if (i >= ET) return;
    int src, dst;
    load_edge(ei, i, E, src, dst);
    atomicAdd(&g_deg[dst], 1);
}

__global__ void scan1_kernel(int n) {          // inclusive scan per 1024-chunk
    __shared__ int s[SCAN_CHUNK];
    int i = blockIdx.x * SCAN_CHUNK + threadIdx.x;
    int v = (i < n) ? g_deg[i] : 0;
    s[threadIdx.x] = v;
    __syncthreads();
#pragma unroll
    for (int off = 1; off < SCAN_CHUNK; off <<= 1) {
        int t = (threadIdx.x >= off) ? s[threadIdx.x - off] : 0;
        __syncthreads();
        s[threadIdx.x] += t;
        __syncthreads();
    }
    if (i < n) g_tmp[i] = s[threadIdx.x];
    if (threadIdx.x == SCAN_CHUNK - 1) g_bsum[blockIdx.x] = s[SCAN_CHUNK - 1];
}

__global__ void scan2_kernel(int nb) {         // exclusive scan of block sums
    __shared__ int s[128];
    int v = (threadIdx.x < nb) ? g_bsum[threadIdx.x] : 0;
    s[threadIdx.x] = v;
    __syncthreads();
#pragma unroll
    for (int off = 1; off < 128; off <<= 1) {
        int t = (threadIdx.x >= off) ? s[threadIdx.x - off] : 0;
        __syncthreads();
        s[threadIdx.x] += t;
        __syncthreads();
    }
    if (threadIdx.x < nb) g_bsum[threadIdx.x] = s[threadIdx.x] - v;
}

__global__ void scan3_kernel(int n) {
    int i = blockIdx.x * SCAN_CHUNK + threadIdx.x;
    if (i >= n) return;
    int start = g_tmp[i] - g_deg[i] + g_bsum[blockIdx.x];
    g_rowptr[i] = start;
    g_cursor[i] = start;
}

__global__ void fill_kernel(const void* ei, int E, int ET) {
    int i = blockIdx.x * blockDim.x + threadIdx.x;
    if (i >= ET) return;
    int src, dst;
    load_edge(ei, i, E, src, dst);
    int pos = atomicAdd(&g_cursor[dst], 1);
    g_csr[pos] = src;
}

// ---------------- dense transform: O[n,64] = A[n,K] @ W[K,64] ---------------
// tile 64 rows x 64 cols, TK=32, 256 threads, 4x4 register block
template <int K>
__global__ void gemm64_kernel(const float* __restrict__ A,
                              const float* __restrict__ W,
                              float* __restrict__ O, int n) {
    __shared__ float xs[64][33];
    __shared__ float ws[32][64];
    int tid = threadIdx.x;
    int rg = tid >> 4;            // 0..15 -> rows rg*4..+3
    int cg = tid & 15;            // 0..15 -> cols cg*4..+3
    int row0 = blockIdx.x * 64;
    float acc[4][4] = {};
    for (int k0 = 0; k0 < K; k0 += 32) {
        // xs: 64x32 floats = 512 float4, 2 per thread
#pragma unroll
        for (int i = 0; i < 2; i++) {
            int idx = i * 256 + tid;      // float4 index
            int r = idx >> 3, c4 = idx & 7;
            float4 v = make_float4(0.f, 0.f, 0.f, 0.f);
            int gr = row0 + r;
            if (gr < n) v = *(const float4*)&A[(size_t)gr * K + k0 + c4 * 4];
            xs[r][c4 * 4 + 0] = v.x; xs[r][c4 * 4 + 1] = v.y;
            xs[r][c4 * 4 + 2] = v.z; xs[r][c4 * 4 + 3] = v.w;
        }
        // ws: 32x64 floats = 512 float4, 2 per thread
#pragma unroll
        for (int i = 0; i < 2; i++) {
            int idx = i * 256 + tid;
            int r = idx >> 4, c4 = idx & 15;
            *(float4*)&ws[r][c4 * 4] = *(const float4*)&W[(size_t)(k0 + r) * 64 + c4 * 4];
        }
        __syncthreads();
#pragma unroll
        for (int kk = 0; kk < 32; kk++) {
            float xv[4];
#pragma unroll
            for (int r = 0; r < 4; r++) xv[r] = xs[rg * 4 + r][kk];
            float4 w = *(float4*)&ws[kk][cg * 4];
#pragma unroll
            for (int r = 0; r < 4; r++) {
                acc[r][0] += xv[r] * w.x; acc[r][1] += xv[r] * w.y;
                acc[r][2] += xv[r] * w.z; acc[r][3] += xv[r] * w.w;
            }
        }
        __syncthreads();
    }
#pragma unroll
    for (int r = 0; r < 4; r++) {
        int gr = row0 + rg * 4 + r;
        if (gr < n)
            *(float4*)&O[(size_t)gr * 64 + cg * 4] =
                make_float4(acc[r][0], acc[r][1], acc[r][2], acc[r][3]);
    }
}

// ---------------- per-node attention scalars --------------------------------
__global__ void sd_kernel(const float* __restrict__ h,
                          const float* __restrict__ a_s,
                          const float* __restrict__ a_d, int n) {
    int v = (blockIdx.x * blockDim.x + threadIdx.x) >> 5;
    int lane = threadIdx.x & 31;
    if (v >= n) return;
    const float* hr = h + (size_t)v * HID;
    float h0 = hr[lane], h1 = hr[lane + 32];
    float s = h0 * a_s[lane] + h1 * a_s[lane + 32];
    float d = h0 * a_d[lane] + h1 * a_d[lane + 32];
#pragma unroll
    for (int o = 16; o; o >>= 1) {
        s += __shfl_xor_sync(0xffffffffu, s, o);
        d += __shfl_xor_sync(0xffffffffu, d, o);
    }
    if (lane == 0) { g_s[v] = s; g_d[v] = d; }
}

// ---------------- fused softmax + aggregation + bias + ELU ------------------
// warp per dst node; CSR gives the incoming-src list.
__global__ void agg_kernel(const float* __restrict__ h,
                           const float* __restrict__ bias,
                           float* __restrict__ out, int n) {
    int v    = (blockIdx.x * blockDim.x + threadIdx.x) >> 5;
    int lane = threadIdx.x & 31;
    if (v >= n) return;
    int e0 = g_rowptr[v], e1 = g_cursor[v];
    float dv = g_d[v];
    float acc0 = 0.f, acc1 = 0.f, den = 0.f;
    for (int e = e0; e < e1; e++) {
        int src = g_csr[e];
        float ev = g_s[src] + dv;
        ev = ev > 0.f ? ev : 0.2f * ev;           // leaky_relu(0.2)
        float p = __expf(ev);                      // no max-shift needed (|e|<~15)
        den += p;
        const float* hs = h + (size_t)src * HID;
        acc0 += p * hs[lane];
        acc1 += p * hs[lane + 32];
    }
    float inv = 1.f / (den + 1e-16f);
    float o0 = acc0 * inv + bias[lane];
    float o1 = acc1 * inv + bias[lane + 32];
    o0 = o0 > 0.f ? o0 : expm1f(o0);               // ELU
    o1 = o1 > 0.f ? o1 : expm1f(o1);
    out[(size_t)v * HID + lane]      = o0;
    out[(size_t)v * HID + lane + 32] = o1;
}

// ---------------- head: out[n,40] = h[n,64] @ Wl + bl -----------------------
// tile 64 rows x 40 cols, 160 threads, 4x4 register block, single K pass
__global__ void logits_kernel(const float* __restrict__ h,
                              const float* __restrict__ Wl,
                              const float* __restrict__ bl,
                              float* __restrict__ out, int n) {
    __shared__ float hs[64][65];
    __shared__ float ws[HID * NCLS];
    __shared__ float bs[NCLS];
    int tid = threadIdx.x;
    int rg = tid / 10;            // 0..15
    int cg = tid % 10;            // 0..9
    int row0 = blockIdx.x * 64;
    // load hs (64x64)
    for (int idx = tid; idx < 64 * 16; idx += 160) {   // float4 granules
        int r = idx >> 4, c4 = idx & 15;
        float4 v = make_float4(0.f, 0.f, 0.f, 0.f);
        int gr = row0 + r;
        if (gr < n) v = *(const float4*)&h[(size_t)gr * HID + c4 * 4];
        hs[r][c4 * 4 + 0] = v.x; hs[r][c4 * 4 + 1] = v.y;
        hs[r][c4 * 4 + 2] = v.z; hs[r][c4 * 4 + 3] = v.w;
    }
    for (int i = tid; i < HID * NCLS; i += 160) ws[i] = Wl[i];
    if (tid < NCLS) bs[tid] = bl[tid];
    __syncthreads();
    float acc[4][4];
#pragma unroll
    for (int r = 0; r < 4; r++)
#pragma unroll
        for (int c = 0; c < 4; c++) acc[r][c] = bs[cg * 4 + c];
#pragma unroll 8
    for (int k = 0; k < HID; k++) {
        float xv[4];
#pragma unroll
        for (int r = 0; r < 4; r++) xv[r] = hs[rg * 4 + r][k];
        float4 w = *(float4*)&ws[k * NCLS + cg * 4];
#pragma unroll
        for (int r = 0; r < 4; r++) {
            acc[r][0] += xv[r] * w.x; acc[r][1] += xv[r] * w.y;
            acc[r][2] += xv[r] * w.z; acc[r][3] += xv[r] * w.w;
        }
    }
#pragma unroll
    for (int r = 0; r < 4; r++) {
        int gr = row0 + rg * 4 + r;
        if (gr < n)
            *(float4*)&out[(size_t)gr * NCLS + cg * 4] =
                make_float4(acc[r][0], acc[r][1], acc[r][2], acc[r][3]);
    }
}

// ---------------- launcher --------------------------------------------------
extern "C" void kernel_launch(void* const* d_in, const int* in_sizes, int n_in,
                              void* d_out, int out_size) {
    const float* x    = (const float*)d_in[0];
    const void*  ei   = d_in[1];
    const float* W0   = (const float*)d_in[2];
    const float* a_s0 = (const float*)d_in[3];
    const float* a_d0 = (const float*)d_in[4];
    const float* b0   = (const float*)d_in[5];
    const float* W1   = (const float*)d_in[6];
    const float* a_s1 = (const float*)d_in[7];
    const float* a_d1 = (const float*)d_in[8];
    const float* b1   = (const float*)d_in[9];
    const float* Wl   = (const float*)d_in[10];
    const float* bl   = (const float*)d_in[11];
    float* out = (float*)d_out;

    int n  = in_sizes[0] / IN_DIM;   // 100000
    int E  = in_sizes[1] / 2;        // 1600000
    int ET = E + n;

    float* hbuf;  cudaGetSymbolAddress((void**)&hbuf, g_h);
    float* abuf;  cudaGetSymbolAddress((void**)&abuf, g_acc);

    int scanBlocks    = (n + SCAN_CHUNK - 1) / SCAN_CHUNK;   // 98
    int edgeBlocks    = (ET + 255) / 256;
    int nodeBlocks    = (n + 255) / 256;
    int nodeWarpBlks  = (n + 7) / 8;

    // ---- CSR build (shared by both layers) ----
    detect_kernel<<<1, 32>>>(ei);
    zero_deg_kernel<<<nodeBlocks, 256>>>(n);
    hist_kernel<<<edgeBlocks, 256>>>(ei, E, ET);
    scan1_kernel<<<scanBlocks, SCAN_CHUNK>>>(n);
    scan2_kernel<<<1, 128>>>(scanBlocks);
    scan3_kernel<<<scanBlocks, SCAN_CHUNK>>>(n);
    fill_kernel<<<edgeBlocks, 256>>>(ei, E, ET);

    // ---- layer 0 ----
    gemm64_kernel<IN_DIM><<<(n + 63) / 64, 256>>>(x, W0, hbuf, n);
    sd_kernel<<<nodeWarpBlks, 256>>>(hbuf, a_s0, a_d0, n);
    agg_kernel<<<nodeWarpBlks, 256>>>(hbuf, b0, abuf, n);

    // ---- layer 1 ----
    gemm64_kernel<HID><<<(n + 63) / 64, 256>>>(abuf, W1, hbuf, n);
    sd_kernel<<<nodeWarpBlks, 256>>>(hbuf, a_s1, a_d1, n);
    agg_kernel<<<nodeWarpBlks, 256>>>(hbuf, b1, abuf, n);

    // ---- head ----
    logits_kernel<<<(n + 63) / 64, 160>>>(abuf, Wl, bl, out, n);
}

// round 3
// speedup vs baseline: 3.5010x; 1.1557x over previous
#include <cuda_runtime.h>
#include <math.h>

#define N_NODES 100000
#define E_MAX   1600000
#define ET_MAX  (E_MAX + N_NODES)
#define HID     64
#define IN_DIM  128
#define NCLS    40
#define SCAN_CHUNK 1024

// ---------------- scratch (device globals; no allocation allowed) ----------
__device__ float g_h[(size_t)N_NODES * HID];    // transformed features h = in @ W
__device__ float g_acc[(size_t)N_NODES * HID];  // layer output / next input
__device__ float g_s[N_NODES];
__device__ float g_d[N_NODES];
__device__ int   g_deg[N_NODES];
__device__ int   g_tmp[N_NODES];
__device__ int   g_rowptr[N_NODES];
__device__ int   g_cursor[N_NODES];             // after fill: row end
__device__ int   g_bsum[128];
__device__ int   g_csr[ET_MAX];                 // src per edge, grouped by dst
__device__ int   g_esrc[ET_MAX];                // decoded int32 edges
__device__ int   g_edst[ET_MAX];
__device__ int   g_is64;

// ---------------- helpers ---------------------------------------------------
__device__ __forceinline__ void load_edge(const void* ei, int i, int E,
                                          int& src, int& dst) {
    if (i >= E) { int v = i - E; src = v; dst = v; return; }   // self-loop
    if (g_is64) {
        const long long* p = (const long long*)ei;
        src = (int)p[i];
        dst = (int)p[(long long)E + i];
    } else {
        const int* p = (const int*)ei;
        src = p[i];
        dst = p[E + i];
    }
}

// ---------------- dtype detect ----------------------------------------------
__global__ void detect_kernel(const void* ei) {
    if (threadIdx.x == 0) {
        const int* p = (const int*)ei;
        int is64 = 1;
        for (int i = 0; i < 1024; i++)
            if (p[2 * i + 1] != 0) { is64 = 0; break; }
        g_is64 = is64;
    }
}

// ---------------- CSR build --------------------------------------------------
__global__ void zero_deg_kernel(int n) {
    int i = blockIdx.x * blockDim.x + threadIdx.x;
    if (i < n) g_deg[i] = 0;
}

// decode edges to int32 + histogram of dst
__global__ void hist_kernel(const void* ei, int E, int ET) {
    int i = blockIdx.x * blockDim.x + threadIdx.x;
    if (i >= ET) return;
    int src, dst;
    load_edge(ei, i, E, src, dst);
    g_esrc[i] = src;
    g_edst[i] = dst;
    atomicAdd(&g_deg[dst], 1);
}

__global__ void scan1_kernel(int n) {          // inclusive scan per 1024-chunk
    __shared__ int s[SCAN_CHUNK];
    int i = blockIdx.x * SCAN_CHUNK + threadIdx.x;
    int v = (i < n) ? g_deg[i] : 0;
    s[threadIdx.x] = v;
    __syncthreads();
#pragma unroll
    for (int off = 1; off < SCAN_CHUNK; off <<= 1) {
        int t = (threadIdx.x >= off) ? s[threadIdx.x - off] : 0;
        __syncthreads();
        s[threadIdx.x] += t;
        __syncthreads();
    }
    if (i < n) g_tmp[i] = s[threadIdx.x];
    if (threadIdx.x == SCAN_CHUNK - 1) g_bsum[blockIdx.x] = s[SCAN_CHUNK - 1];
}

__global__ void scan2_kernel(int nb) {         // exclusive scan of block sums
    __shared__ int s[128];
    int v = (threadIdx.x < nb) ? g_bsum[threadIdx.x] : 0;
    s[threadIdx.x] = v;
    __syncthreads();
#pragma unroll
    for (int off = 1; off < 128; off <<= 1) {
        int t = (threadIdx.x >= off) ? s[threadIdx.x - off] : 0;
        __syncthreads();
        s[threadIdx.x] += t;
        __syncthreads();
    }
    if (threadIdx.x < nb) g_bsum[threadIdx.x] = s[threadIdx.x] - v;
}

__global__ void scan3_kernel(int n) {
    int i = blockIdx.x * SCAN_CHUNK + threadIdx.x;
    if (i >= n) return;
    int start = g_tmp[i] - g_deg[i] + g_bsum[blockIdx.x];
    g_rowptr[i] = start;
    g_cursor[i] = start;
}

__global__ void fill_kernel(int ET) {
    int i = blockIdx.x * blockDim.x + threadIdx.x;
    if (i >= ET) return;
    int src = g_esrc[i];
    int dst = g_edst[i];
    int pos = atomicAdd(&g_cursor[dst], 1);
    g_csr[pos] = src;
}

// ---------------- dense transform + fused attention scalars -----------------
// O[n,64] = A[n,K] @ W[K,64]; also s[v]=O[v]·a_s, d[v]=O[v]·a_d.
// tile 64 rows x 64 cols, TK=32, 256 threads, 4x4 register block.
template <int K>
__global__ void gemm64_kernel(const float* __restrict__ A,
                              const float* __restrict__ W,
                              const float* __restrict__ a_s,
                              const float* __restrict__ a_d,
                              float* __restrict__ O, int n) {
    __shared__ float xs[64][33];
    __shared__ float ws[32][64];
    int tid = threadIdx.x;
    int rg = tid >> 4;            // 0..15 -> rows rg*4..+3
    int cg = tid & 15;            // 0..15 -> cols cg*4..+3
    int row0 = blockIdx.x * 64;
    float4 asv = *(const float4*)&a_s[cg * 4];
    float4 adv = *(const float4*)&a_d[cg * 4];
    float acc[4][4] = {};
    for (int k0 = 0; k0 < K; k0 += 32) {
#pragma unroll
        for (int i = 0; i < 2; i++) {
            int idx = i * 256 + tid;      // float4 index into 64x32 x-tile
            int r = idx >> 3, c4 = idx & 7;
            float4 v = make_float4(0.f, 0.f, 0.f, 0.f);
            int gr = row0 + r;
            if (gr < n) v = *(const float4*)&A[(size_t)gr * K + k0 + c4 * 4];
            xs[r][c4 * 4 + 0] = v.x; xs[r][c4 * 4 + 1] = v.y;
            xs[r][c4 * 4 + 2] = v.z; xs[r][c4 * 4 + 3] = v.w;
        }
#pragma unroll
        for (int i = 0; i < 2; i++) {
            int idx = i * 256 + tid;      // float4 index into 32x64 w-tile
            int r = idx >> 4, c4 = idx & 15;
            *(float4*)&ws[r][c4 * 4] = *(const float4*)&W[(size_t)(k0 + r) * 64 + c4 * 4];
        }
        __syncthreads();
#pragma unroll
        for (int kk = 0; kk < 32; kk++) {
            float xv[4];
#pragma unroll
            for (int r = 0; r < 4; r++) xv[r] = xs[rg * 4 + r][kk];
            float4 w = *(float4*)&ws[kk][cg * 4];
#pragma unroll
            for (int r = 0; r < 4; r++) {
                acc[r][0] += xv[r] * w.x; acc[r][1] += xv[r] * w.y;
                acc[r][2] += xv[r] * w.z; acc[r][3] += xv[r] * w.w;
            }
        }
        __syncthreads();
    }
#pragma unroll
    for (int r = 0; r < 4; r++) {
        int gr = row0 + rg * 4 + r;
        if (gr < n)
            *(float4*)&O[(size_t)gr * 64 + cg * 4] =
                make_float4(acc[r][0], acc[r][1], acc[r][2], acc[r][3]);
        // fused s/d: reduce across the 16 threads (one half-warp) sharing rg
        float sv = acc[r][0] * asv.x + acc[r][1] * asv.y +
                   acc[r][2] * asv.z + acc[r][3] * asv.w;
        float dv = acc[r][0] * adv.x + acc[r][1] * adv.y +
                   acc[r][2] * adv.z + acc[r][3] * adv.w;
#pragma unroll
        for (int off = 8; off; off >>= 1) {
            sv += __shfl_down_sync(0xffffffffu, sv, off, 16);
            dv += __shfl_down_sync(0xffffffffu, dv, off, 16);
        }
        if (cg == 0 && gr < n) { g_s[gr] = sv; g_d[gr] = dv; }
    }
}

// ---------------- fused softmax + aggregation + bias + ELU ------------------
// HALF-warp (16 lanes) per dst node; lane handles 4 feature channels (float4).
__device__ __forceinline__ float att_p(int src, float dv) {
    float ev = g_s[src] + dv;
    ev = ev > 0.f ? ev : 0.2f * ev;                // leaky_relu(0.2)
    return __expf(ev);                              // logits bounded, no max-shift
}

__global__ void agg_kernel(const float* __restrict__ h,
                           const float* __restrict__ bias,
                           float* __restrict__ out, int n) {
    int v = (blockIdx.x * blockDim.x + threadIdx.x) >> 4;
    int l = threadIdx.x & 15;
    if (v >= n) return;
    int e0 = g_rowptr[v], e1 = g_cursor[v];
    float dv = g_d[v];
    float4 acc = make_float4(0.f, 0.f, 0.f, 0.f);
    float den = 0.f;
    int e = e0;
    for (; e + 1 < e1; e += 2) {                    // 2-edge unroll for MLP
        int s0 = g_csr[e], s1 = g_csr[e + 1];
        float p0 = att_p(s0, dv);
        float p1 = att_p(s1, dv);
        float4 h0 = *(const float4*)&h[(size_t)s0 * HID + l * 4];
        float4 h1 = *(const float4*)&h[(size_t)s1 * HID + l * 4];
        den += p0 + p1;
        acc.x += p0 * h0.x + p1 * h1.x;
        acc.y += p0 * h0.y + p1 * h1.y;
        acc.z += p0 * h0.z + p1 * h1.z;
        acc.w += p0 * h0.w + p1 * h1.w;
    }
    if (e < e1) {
        int s0 = g_csr[e];
        float p0 = att_p(s0, dv);
        float4 h0 = *(const float4*)&h[(size_t)s0 * HID + l * 4];
        den += p0;
        acc.x += p0 * h0.x; acc.y += p0 * h0.y;
        acc.z += p0 * h0.z; acc.w += p0 * h0.w;
    }
    float inv = 1.f / (den + 1e-16f);
    float4 b4 = *(const float4*)&bias[l * 4];
    float4 o;
    o.x = acc.x * inv + b4.x;
    o.y = acc.y * inv + b4.y;
    o.z = acc.z * inv + b4.z;
    o.w = acc.w * inv + b4.w;
    o.x = o.x > 0.f ? o.x : expm1f(o.x);            // ELU
    o.y = o.y > 0.f ? o.y : expm1f(o.y);
    o.z = o.z > 0.f ? o.z : expm1f(o.z);
    o.w = o.w > 0.f ? o.w : expm1f(o.w);
    *(float4*)&out[(size_t)v * HID + l * 4] = o;
}

// ---------------- head: out[n,40] = h[n,64] @ Wl + bl -----------------------
__global__ void logits_kernel(const float* __restrict__ h,
                              const float* __restrict__ Wl,
                              const float* __restrict__ bl,
                              float* __restrict__ out, int n) {
    __shared__ float hs[64][65];
    __shared__ float ws[HID * NCLS];
    __shared__ float bs[NCLS];
    int tid = threadIdx.x;
    int rg = tid / 10;            // 0..15
    int cg = tid % 10;            // 0..9
    int row0 = blockIdx.x * 64;
    for (int idx = tid; idx < 64 * 16; idx += 160) {   // float4 granules
        int r = idx >> 4, c4 = idx & 15;
        float4 v = make_float4(0.f, 0.f, 0.f, 0.f);
        int gr = row0 + r;
        if (gr < n) v = *(const float4*)&h[(size_t)gr * HID + c4 * 4];
        hs[r][c4 * 4 + 0] = v.x; hs[r][c4 * 4 + 1] = v.y;
        hs[r][c4 * 4 + 2] = v.z; hs[r][c4 * 4 + 3] = v.w;
    }
    for (int i = tid; i < HID * NCLS; i += 160) ws[i] = Wl[i];
    if (tid < NCLS) bs[tid] = bl[tid];
    __syncthreads();
    float acc[4][4];
#pragma unroll
    for (int r = 0; r < 4; r++)
#pragma unroll
        for (int c = 0; c < 4; c++) acc[r][c] = bs[cg * 4 + c];
#pragma unroll 8
    for (int k = 0; k < HID; k++) {
        float xv[4];
#pragma unroll
        for (int r = 0; r < 4; r++) xv[r] = hs[rg * 4 + r][k];
        float4 w = *(float4*)&ws[k * NCLS + cg * 4];
#pragma unroll
        for (int r = 0; r < 4; r++) {
            acc[r][0] += xv[r] * w.x; acc[r][1] += xv[r] * w.y;
            acc[r][2] += xv[r] * w.z; acc[r][3] += xv[r] * w.w;
        }
    }
#pragma unroll
    for (int r = 0; r < 4; r++) {
        int gr = row0 + rg * 4 + r;
        if (gr < n)
            *(float4*)&out[(size_t)gr * NCLS + cg * 4] =
                make_float4(acc[r][0], acc[r][1], acc[r][2], acc[r][3]);
    }
}

// ---------------- launcher --------------------------------------------------
extern "C" void kernel_launch(void* const* d_in, const int* in_sizes, int n_in,
                              void* d_out, int out_size) {
    const float* x    = (const float*)d_in[0];
    const void*  ei   = d_in[1];
    const float* W0   = (const float*)d_in[2];
    const float* a_s0 = (const float*)d_in[3];
    const float* a_d0 = (const float*)d_in[4];
    const float* b0   = (const float*)d_in[5];
    const float* W1   = (const float*)d_in[6];
    const float* a_s1 = (const float*)d_in[7];
    const float* a_d1 = (const float*)d_in[8];
    const float* b1   = (const float*)d_in[9];
    const float* Wl   = (const float*)d_in[10];
    const float* bl   = (const float*)d_in[11];
    float* out = (float*)d_out;

    int n  = in_sizes[0] / IN_DIM;   // 100000
    int E  = in_sizes[1] / 2;        // 1600000
    int ET = E + n;

    float* hbuf;  cudaGetSymbolAddress((void**)&hbuf, g_h);
    float* abuf;  cudaGetSymbolAddress((void**)&abuf, g_acc);

    int scanBlocks   = (n + SCAN_CHUNK - 1) / SCAN_CHUNK;   // 98
    int edgeBlocks   = (ET + 255) / 256;
    int nodeBlocks   = (n + 255) / 256;
    int hwBlocks     = (n + 15) / 16;       // 16 half-warp nodes per 256-thr block

    // ---- CSR build (shared by both layers) ----
    detect_kernel<<<1, 32>>>(ei);
    zero_deg_kernel<<<nodeBlocks, 256>>>(n);
    hist_kernel<<<edgeBlocks, 256>>>(ei, E, ET);
    scan1_kernel<<<scanBlocks, SCAN_CHUNK>>>(n);
    scan2_kernel<<<1, 128>>>(scanBlocks);
    scan3_kernel<<<scanBlocks, SCAN_CHUNK>>>(n);
    fill_kernel<<<edgeBlocks, 256>>>(ET);

    // ---- layer 0 ----
    gemm64_kernel<IN_DIM><<<(n + 63) / 64, 256>>>(x, W0, a_s0, a_d0, hbuf, n);
    agg_kernel<<<hwBlocks, 256>>>(hbuf, b0, abuf, n);

    // ---- layer 1 ----
    gemm64_kernel<HID><<<(n + 63) / 64, 256>>>(abuf, W1, a_s1, a_d1, hbuf, n);
    agg_kernel<<<hwBlocks, 256>>>(hbuf, b1, abuf, n);

    // ---- head ----
    logits_kernel<<<(n + 63) / 64, 160>>>(abuf, Wl, bl, out, n);
}